// round 6
// baseline (speedup 1.0000x reference)
#include <cuda_runtime.h>
#include <cuda_bf16.h>

#define N_NODES  50000
#define D_IN     128
#define D_HID    16
#define E_MAX    800000
#define CAP      128            // bucket capacity per node (Poisson(16): overflow prob ~0)
#define CAP_SHIFT 7

// ---- scratch (__device__ globals; zero-initialized at load; self-cleaning) ----
__device__ int g_cnt[N_NODES];                    // degree; reset by k_gather2out
__device__ int g_eidx[N_NODES * CAP];             // src buckets, one fixed region per dst
__device__ __align__(16) float g_h1s[N_NODES * D_HID];  // (x@W1) * dinv_i
__device__ __align__(16) float g_zs [N_NODES * D_HID];  // z * dinv_i

// ld.global.cg float4: bypass L1, no line fill (gathered data has no L1 reuse)
__device__ __forceinline__ float4 ldcg4(const float* p) {
    float4 v;
    asm volatile("ld.global.cg.v4.f32 {%0,%1,%2,%3}, [%4];"
                 : "=f"(v.x), "=f"(v.y), "=f"(v.z), "=f"(v.w) : "l"(p));
    return v;
}
__device__ __forceinline__ int ldcg1(const int* p) {
    int v;
    asm volatile("ld.global.cg.s32 %0, [%1];" : "=r"(v) : "l"(p));
    return v;
}

// ---------------------------------------------------------------------------
// Single-pass bucket build: 8 edges per thread for deep atomic MLP.
__global__ void k_fill(const int* __restrict__ src, const int* __restrict__ dst, int E) {
    int t = blockIdx.x * blockDim.x + threadIdx.x;
    int e = t * 8;
    if (e + 7 < E) {
        int4 d0 = *(const int4*)(dst + e);
        int4 d1 = *(const int4*)(dst + e + 4);
        int4 s0 = *(const int4*)(src + e);
        int4 s1 = *(const int4*)(src + e + 4);
        int p0 = atomicAdd(&g_cnt[d0.x], 1);
        int p1 = atomicAdd(&g_cnt[d0.y], 1);
        int p2 = atomicAdd(&g_cnt[d0.z], 1);
        int p3 = atomicAdd(&g_cnt[d0.w], 1);
        int p4 = atomicAdd(&g_cnt[d1.x], 1);
        int p5 = atomicAdd(&g_cnt[d1.y], 1);
        int p6 = atomicAdd(&g_cnt[d1.z], 1);
        int p7 = atomicAdd(&g_cnt[d1.w], 1);
        if (p0 < CAP) g_eidx[(d0.x << CAP_SHIFT) + p0] = s0.x;
        if (p1 < CAP) g_eidx[(d0.y << CAP_SHIFT) + p1] = s0.y;
        if (p2 < CAP) g_eidx[(d0.z << CAP_SHIFT) + p2] = s0.z;
        if (p3 < CAP) g_eidx[(d0.w << CAP_SHIFT) + p3] = s0.w;
        if (p4 < CAP) g_eidx[(d1.x << CAP_SHIFT) + p4] = s1.x;
        if (p5 < CAP) g_eidx[(d1.y << CAP_SHIFT) + p5] = s1.y;
        if (p6 < CAP) g_eidx[(d1.z << CAP_SHIFT) + p6] = s1.z;
        if (p7 < CAP) g_eidx[(d1.w << CAP_SHIFT) + p7] = s1.w;
    } else {
        for (; e < E; e++) {
            int d = dst[e];
            int p = atomicAdd(&g_cnt[d], 1);
            if (p < CAP) g_eidx[(d << CAP_SHIFT) + p] = src[e];
        }
    }
}

// ---------------------------------------------------------------------------
// h1s = (x @ W1) * dinv_i : 4 threads per node; dinv computed inline from g_cnt.
__global__ void k_gemm1(const float* __restrict__ x, const float* __restrict__ W1) {
    __shared__ float sW[D_IN * D_HID];
    for (int t = threadIdx.x; t < D_IN * D_HID; t += blockDim.x) sW[t] = W1[t];
    __syncthreads();
    int t = blockIdx.x * blockDim.x + threadIdx.x;
    int i = t >> 2, q = t & 3;
    if (i >= N_NODES) return;

    float a0 = 0.f, a1 = 0.f, a2 = 0.f, a3 = 0.f;
    const float* xr = x + (size_t)i * D_IN;
#pragma unroll
    for (int j4 = 0; j4 < 32; j4++) {
        float4 v = ldcg4(xr + j4 * 4);      // streaming, read-once
        float4 r0 = *(const float4*)&sW[(j4 * 4 + 0) * D_HID + q * 4];
        float4 r1 = *(const float4*)&sW[(j4 * 4 + 1) * D_HID + q * 4];
        float4 r2 = *(const float4*)&sW[(j4 * 4 + 2) * D_HID + q * 4];
        float4 r3 = *(const float4*)&sW[(j4 * 4 + 3) * D_HID + q * 4];
        a0 += v.x * r0.x + v.y * r1.x + v.z * r2.x + v.w * r3.x;
        a1 += v.x * r0.y + v.y * r1.y + v.z * r2.y + v.w * r3.y;
        a2 += v.x * r0.z + v.y * r1.z + v.z * r2.z + v.w * r3.z;
        a3 += v.x * r0.w + v.y * r1.w + v.z * r2.w + v.w * r3.w;
    }
    float di = rsqrtf((float)g_cnt[i] + 1.0f);
    *(float4*)(g_h1s + (size_t)i * D_HID + q * 4) =
        make_float4(a0 * di, a1 * di, a2 * di, a3 * di);
}

// ---------------------------------------------------------------------------
// gather pass 1: zs_i = (dinv_i * (Σ_{src∈N(i)} h1s[src] + h1s[i]) + b1) * dinv_i
// warp per node; 4-lane group per edge; all gather loads bypass L1 (.cg)
__global__ void k_gather1(const float* __restrict__ b1) {
    int gw = (blockIdx.x * blockDim.x + threadIdx.x) >> 5;
    if (gw >= N_NODES) return;
    int lane = threadIdx.x & 31;
    int q = lane & 3, s = lane >> 2;

    int cntRaw = g_cnt[gw];
    int cnt = min(cntRaw, CAP);
    int base = gw << CAP_SHIFT;
    float4 acc = make_float4(0.f, 0.f, 0.f, 0.f);
#pragma unroll 2
    for (int e = s; e < cnt; e += 8) {
        int sn = ldcg1(&g_eidx[base + e]);
        float4 f = ldcg4(g_h1s + (size_t)sn * D_HID + q * 4);
        acc.x += f.x; acc.y += f.y; acc.z += f.z; acc.w += f.w;
    }
    if (s == 0) {  // self loop
        float4 f = ldcg4(g_h1s + (size_t)gw * D_HID + q * 4);
        acc.x += f.x; acc.y += f.y; acc.z += f.z; acc.w += f.w;
    }
#pragma unroll
    for (int m = 4; m < 32; m <<= 1) {
        acc.x += __shfl_xor_sync(0xffffffffu, acc.x, m);
        acc.y += __shfl_xor_sync(0xffffffffu, acc.y, m);
        acc.z += __shfl_xor_sync(0xffffffffu, acc.z, m);
        acc.w += __shfl_xor_sync(0xffffffffu, acc.w, m);
    }
    if (lane < 4) {
        float di = rsqrtf((float)cntRaw + 1.0f);
        float4 b = ((const float4*)b1)[q];
        float4 z;
        z.x = (di * acc.x + b.x) * di;
        z.y = (di * acc.y + b.y) * di;
        z.z = (di * acc.z + b.z) * di;
        z.w = (di * acc.w + b.w) * di;
        *(float4*)(g_zs + (size_t)gw * D_HID + q * 4) = z;
    }
}

// ---------------------------------------------------------------------------
// gather pass 2 fused with decoder GEMM; resets g_cnt for the next replay.
__global__ void k_gather2out(const float* __restrict__ W2, const float* __restrict__ b2,
                             float* __restrict__ out) {
    __shared__ float sW[D_HID * D_IN];
    for (int t = threadIdx.x; t < D_HID * D_IN; t += blockDim.x) sW[t] = W2[t];
    __syncthreads();

    int gw = (blockIdx.x * blockDim.x + threadIdx.x) >> 5;
    int lane = threadIdx.x & 31;
    if (gw >= N_NODES) return;

    int q = lane & 3, s = lane >> 2;
    int cntRaw = g_cnt[gw];
    int cnt = min(cntRaw, CAP);
    int base = gw << CAP_SHIFT;
    float4 acc = make_float4(0.f, 0.f, 0.f, 0.f);
#pragma unroll 2
    for (int e = s; e < cnt; e += 8) {
        int sn = ldcg1(&g_eidx[base + e]);
        float4 f = ldcg4(g_zs + (size_t)sn * D_HID + q * 4);
        acc.x += f.x; acc.y += f.y; acc.z += f.z; acc.w += f.w;
    }
    if (s == 0) {  // self loop
        float4 f = ldcg4(g_zs + (size_t)gw * D_HID + q * 4);
        acc.x += f.x; acc.y += f.y; acc.z += f.z; acc.w += f.w;
    }
#pragma unroll
    for (int m = 4; m < 32; m <<= 1) {
        acc.x += __shfl_xor_sync(0xffffffffu, acc.x, m);
        acc.y += __shfl_xor_sync(0xffffffffu, acc.y, m);
        acc.z += __shfl_xor_sync(0xffffffffu, acc.z, m);
        acc.w += __shfl_xor_sync(0xffffffffu, acc.w, m);
    }
    // lane with index q holds components [4q,4q+4); broadcast all 16
    float di = rsqrtf((float)cntRaw + 1.0f);
    float v[D_HID];
#pragma unroll
    for (int k = 0; k < D_HID; k++) {
        float comp = ((k & 3) == 0) ? acc.x : ((k & 3) == 1) ? acc.y
                   : ((k & 3) == 2) ? acc.z : acc.w;
        v[k] = __shfl_sync(0xffffffffu, comp, k >> 2) * di;
    }
    if (lane == 0) g_cnt[gw] = 0;       // self-clean for next replay

    float4 a = *(const float4*)(b2 + lane * 4);
#pragma unroll
    for (int k = 0; k < D_HID; k++) {
        float4 w = *(const float4*)&sW[k * D_IN + lane * 4];
        a.x += v[k] * w.x;
        a.y += v[k] * w.y;
        a.z += v[k] * w.z;
        a.w += v[k] * w.w;
    }
    *(float4*)(out + (size_t)gw * D_IN + lane * 4) = a;
}

// ---------------------------------------------------------------------------
extern "C" void kernel_launch(void* const* d_in, const int* in_sizes, int n_in,
                              void* d_out, int out_size) {
    const float* x  = (const float*)d_in[0];
    const int*   ei = (const int*)  d_in[1];
    const float* W1 = (const float*)d_in[2];
    const float* b1 = (const float*)d_in[3];
    const float* W2 = (const float*)d_in[4];
    const float* b2 = (const float*)d_in[5];
    float* out = (float*)d_out;

    int E = in_sizes[1] / 2;
    const int* src = ei;
    const int* dst = ei + E;

    const int T = 256;
    int eThreads = (E + 7) / 8;
    k_fill <<<(eThreads + T - 1) / T, T>>>(src, dst, E);
    k_gemm1<<<(N_NODES * 4 + T - 1) / T, T>>>(x, W1);
    k_gather1<<<(N_NODES * 32 + T - 1) / T, T>>>(b1);
    k_gather2out<<<(N_NODES * 32 + T - 1) / T, T>>>(W2, b2, out);
}

// round 7
// speedup vs baseline: 1.0196x; 1.0196x over previous
#include <cuda_runtime.h>
#include <cuda_bf16.h>

#define N_NODES  50000
#define D_IN     128
#define D_HID    16
#define E_MAX    800000
#define CAP      128            // bucket capacity per node (Poisson(16): overflow prob ~0)
#define CAP_SHIFT 7

// ---- scratch (__device__ globals; zero-initialized at load; self-cleaning) ----
__device__ int g_cnt[N_NODES];                    // degree; reset by k_gather2out
__device__ int g_eidx[N_NODES * CAP];             // src buckets, one fixed region per dst
__device__ __align__(16) float g_h1s[N_NODES * D_HID];  // (x@W1) * dinv_i
__device__ __align__(16) float g_zs [N_NODES * D_HID];  // z * dinv_i

__device__ __forceinline__ float4 ldcg4(const float* p) {
    float4 v;
    asm volatile("ld.global.cg.v4.f32 {%0,%1,%2,%3}, [%4];"
                 : "=f"(v.x), "=f"(v.y), "=f"(v.z), "=f"(v.w) : "l"(p));
    return v;
}
__device__ __forceinline__ int ldcg1(const int* p) {
    int v;
    asm volatile("ld.global.cg.s32 %0, [%1];" : "=r"(v) : "l"(p));
    return v;
}

// ---------------------------------------------------------------------------
// Single-pass bucket build: 16 edges per thread for deep atomic MLP.
__global__ void k_fill(const int* __restrict__ src, const int* __restrict__ dst, int E) {
    int t = blockIdx.x * blockDim.x + threadIdx.x;
    int e0 = t * 16;
    if (e0 + 15 < E) {
        int4 d[4], s[4];
#pragma unroll
        for (int c = 0; c < 4; c++) {
            d[c] = *(const int4*)(dst + e0 + c * 4);
            s[c] = *(const int4*)(src + e0 + c * 4);
        }
        int p[16];
#pragma unroll
        for (int c = 0; c < 4; c++) {
            p[c * 4 + 0] = atomicAdd(&g_cnt[d[c].x], 1);
            p[c * 4 + 1] = atomicAdd(&g_cnt[d[c].y], 1);
            p[c * 4 + 2] = atomicAdd(&g_cnt[d[c].z], 1);
            p[c * 4 + 3] = atomicAdd(&g_cnt[d[c].w], 1);
        }
#pragma unroll
        for (int c = 0; c < 4; c++) {
            if (p[c*4+0] < CAP) g_eidx[(d[c].x << CAP_SHIFT) + p[c*4+0]] = s[c].x;
            if (p[c*4+1] < CAP) g_eidx[(d[c].y << CAP_SHIFT) + p[c*4+1]] = s[c].y;
            if (p[c*4+2] < CAP) g_eidx[(d[c].z << CAP_SHIFT) + p[c*4+2]] = s[c].z;
            if (p[c*4+3] < CAP) g_eidx[(d[c].w << CAP_SHIFT) + p[c*4+3]] = s[c].w;
        }
    } else {
        for (int e = e0; e < E; e++) {
            int dd = dst[e];
            int pp = atomicAdd(&g_cnt[dd], 1);
            if (pp < CAP) g_eidx[(dd << CAP_SHIFT) + pp] = src[e];
        }
    }
}

// ---------------------------------------------------------------------------
// h1s = (x @ W1) * dinv_i. Block tiles 64 nodes; x staged once through smem.
#define G1_TILE 64
#define G1_XPAD 132   // floats per row in smem (pad: rotates banks, keeps 16B align)
__global__ void k_gemm1(const float* __restrict__ x, const float* __restrict__ W1) {
    __shared__ float sW[D_IN * D_HID];            // 8 KB
    __shared__ float sX[G1_TILE * G1_XPAD];       // ~33 KB
    int tid = threadIdx.x;
    for (int t = tid; t < D_IN * D_HID; t += blockDim.x) sW[t] = W1[t];

    int row0 = blockIdx.x * G1_TILE;
    // stage 64 rows of x (float4 coalesced)
#pragma unroll
    for (int it = 0; it < 8; it++) {
        int pos = tid + it * 256;                 // 2048 float4 slots
        int r = pos >> 5, c4 = pos & 31;
        if (row0 + r < N_NODES) {
            float4 v = ldcg4(x + (size_t)(row0 + r) * D_IN + c4 * 4);
            *(float4*)&sX[r * G1_XPAD + c4 * 4] = v;
        }
    }
    __syncthreads();

    int local = tid >> 2, q = tid & 3;
    int i = row0 + local;
    if (i >= N_NODES) return;

    float a0 = 0.f, a1 = 0.f, a2 = 0.f, a3 = 0.f;
#pragma unroll
    for (int j4 = 0; j4 < 32; j4++) {
        float4 v = *(const float4*)&sX[local * G1_XPAD + j4 * 4];
        float4 r0 = *(const float4*)&sW[(j4 * 4 + 0) * D_HID + q * 4];
        float4 r1 = *(const float4*)&sW[(j4 * 4 + 1) * D_HID + q * 4];
        float4 r2 = *(const float4*)&sW[(j4 * 4 + 2) * D_HID + q * 4];
        float4 r3 = *(const float4*)&sW[(j4 * 4 + 3) * D_HID + q * 4];
        a0 += v.x * r0.x + v.y * r1.x + v.z * r2.x + v.w * r3.x;
        a1 += v.x * r0.y + v.y * r1.y + v.z * r2.y + v.w * r3.y;
        a2 += v.x * r0.z + v.y * r1.z + v.z * r2.z + v.w * r3.z;
        a3 += v.x * r0.w + v.y * r1.w + v.z * r2.w + v.w * r3.w;
    }
    float di = rsqrtf((float)g_cnt[i] + 1.0f);
    *(float4*)(g_h1s + (size_t)i * D_HID + q * 4) =
        make_float4(a0 * di, a1 * di, a2 * di, a3 * di);
}

// ---------------------------------------------------------------------------
// gather pass 1: zs_i = (dinv_i * (Σ h1s[src] + h1s[i]) + b1) * dinv_i
__global__ void k_gather1(const float* __restrict__ b1) {
    int gw = (blockIdx.x * blockDim.x + threadIdx.x) >> 5;
    if (gw >= N_NODES) return;
    int lane = threadIdx.x & 31;
    int q = lane & 3, s = lane >> 2;

    int cntRaw = g_cnt[gw];
    int cnt = min(cntRaw, CAP);
    int base = gw << CAP_SHIFT;
    float4 acc = make_float4(0.f, 0.f, 0.f, 0.f);
#pragma unroll 2
    for (int e = s; e < cnt; e += 8) {
        int sn = ldcg1(&g_eidx[base + e]);
        float4 f = ldcg4(g_h1s + (size_t)sn * D_HID + q * 4);
        acc.x += f.x; acc.y += f.y; acc.z += f.z; acc.w += f.w;
    }
    if (s == 0) {  // self loop
        float4 f = ldcg4(g_h1s + (size_t)gw * D_HID + q * 4);
        acc.x += f.x; acc.y += f.y; acc.z += f.z; acc.w += f.w;
    }
#pragma unroll
    for (int m = 4; m < 32; m <<= 1) {
        acc.x += __shfl_xor_sync(0xffffffffu, acc.x, m);
        acc.y += __shfl_xor_sync(0xffffffffu, acc.y, m);
        acc.z += __shfl_xor_sync(0xffffffffu, acc.z, m);
        acc.w += __shfl_xor_sync(0xffffffffu, acc.w, m);
    }
    if (lane < 4) {
        float di = rsqrtf((float)cntRaw + 1.0f);
        float4 b = ((const float4*)b1)[q];
        float4 z;
        z.x = (di * acc.x + b.x) * di;
        z.y = (di * acc.y + b.y) * di;
        z.z = (di * acc.z + b.z) * di;
        z.w = (di * acc.w + b.w) * di;
        *(float4*)(g_zs + (size_t)gw * D_HID + q * 4) = z;
    }
}

// ---------------------------------------------------------------------------
// gather pass 2 + decoder GEMM.
// Phase A: warp-per-node gather -> v vectors into smem (8 nodes/block).
// Phase B: warp w computes out columns [16w,16w+16) for ALL 8 nodes, so each
// 64B LDS.128 of W2 is reused by 8 nodes (W2 smem traffic 8KB -> 1KB per node).
#define SV_STRIDE 36   // floats; 16B-aligned, banks 4n mod 32 all distinct
__global__ void k_gather2out(const float* __restrict__ W2, const float* __restrict__ b2,
                             float* __restrict__ out) {
    __shared__ float sW[D_HID * D_IN];
    __shared__ float sv[8 * SV_STRIDE];
    for (int t = threadIdx.x; t < D_HID * D_IN; t += blockDim.x) sW[t] = W2[t];

    int w = threadIdx.x >> 5;
    int lane = threadIdx.x & 31;
    int gw = blockIdx.x * 8 + w;                 // 6250*8 == 50000 exactly

    // ---- Phase A: gather & reduce for node gw ----
    {
        int q = lane & 3, s = lane >> 2;
        int cntRaw = g_cnt[gw];
        int cnt = min(cntRaw, CAP);
        int base = gw << CAP_SHIFT;
        float4 acc = make_float4(0.f, 0.f, 0.f, 0.f);
#pragma unroll 2
        for (int e = s; e < cnt; e += 8) {
            int sn = ldcg1(&g_eidx[base + e]);
            float4 f = ldcg4(g_zs + (size_t)sn * D_HID + q * 4);
            acc.x += f.x; acc.y += f.y; acc.z += f.z; acc.w += f.w;
        }
        if (s == 0) {  // self loop
            float4 f = ldcg4(g_zs + (size_t)gw * D_HID + q * 4);
            acc.x += f.x; acc.y += f.y; acc.z += f.z; acc.w += f.w;
        }
#pragma unroll
        for (int m = 4; m < 32; m <<= 1) {
            acc.x += __shfl_xor_sync(0xffffffffu, acc.x, m);
            acc.y += __shfl_xor_sync(0xffffffffu, acc.y, m);
            acc.z += __shfl_xor_sync(0xffffffffu, acc.z, m);
            acc.w += __shfl_xor_sync(0xffffffffu, acc.w, m);
        }
        if (lane < 4) {
            float di = rsqrtf((float)cntRaw + 1.0f);
            *(float4*)&sv[w * SV_STRIDE + q * 4] =
                make_float4(di * acc.x, di * acc.y, di * acc.z, di * acc.w);
        }
        if (lane == 0) g_cnt[gw] = 0;           // self-clean for next replay
    }
    __syncthreads();

    // ---- Phase B: warp w -> columns [16w, 16w+16) of all 8 nodes ----
    int n  = lane >> 2;                          // node within block
    int c4 = lane & 3;                           // 4-col group within warp's 16 cols
    int col = w * 16 + c4 * 4;

    float4 vv[4];                                // v[n][0..16) for this lane's node
#pragma unroll
    for (int kk = 0; kk < 4; kk++)
        vv[kk] = *(const float4*)&sv[n * SV_STRIDE + kk * 4];

    float4 a = *(const float4*)(b2 + col);
#pragma unroll
    for (int k = 0; k < D_HID; k++) {
        float vk = (k & 3) == 0 ? vv[k >> 2].x : (k & 3) == 1 ? vv[k >> 2].y
                 : (k & 3) == 2 ? vv[k >> 2].z : vv[k >> 2].w;
        float4 wv = *(const float4*)&sW[k * D_IN + col];
        a.x += vk * wv.x;
        a.y += vk * wv.y;
        a.z += vk * wv.z;
        a.w += vk * wv.w;
    }
    *(float4*)(out + (size_t)(blockIdx.x * 8 + n) * D_IN + col) = a;
}

// ---------------------------------------------------------------------------
extern "C" void kernel_launch(void* const* d_in, const int* in_sizes, int n_in,
                              void* d_out, int out_size) {
    const float* x  = (const float*)d_in[0];
    const int*   ei = (const int*)  d_in[1];
    const float* W1 = (const float*)d_in[2];
    const float* b1 = (const float*)d_in[3];
    const float* W2 = (const float*)d_in[4];
    const float* b2 = (const float*)d_in[5];
    float* out = (float*)d_out;

    int E = in_sizes[1] / 2;
    const int* src = ei;
    const int* dst = ei + E;

    const int T = 256;
    int eThreads = (E + 15) / 16;
    k_fill <<<(eThreads + T - 1) / T, T>>>(src, dst, E);
    k_gemm1<<<(N_NODES + G1_TILE - 1) / G1_TILE, T>>>(x, W1);
    k_gather1<<<(N_NODES * 32 + T - 1) / T, T>>>(b1);
    k_gather2out<<<N_NODES / 8, T>>>(W2, b2, out);
}